// round 14
// baseline (speedup 1.0000x reference)
#include <cuda_runtime.h>

// Fused quadratic-form SH shading: out[b,p] = n4^T M(b) n4, n4=(nx,ny,nz,1).
// M symmetric -> 10 coefficients computed per-thread from light[b,0..8]
// (warp-uniform loads). Pure HBM stream. Inline-asm liveness barriers after
// the 12 LDG.128 pin every loaded value in a register, forcing ptxas to issue
// all loads before any FMA (true SASS-level MLP=12).

#define C1_ 0.429043f
#define C2_ 0.511664f
#define C3_ 0.743152f
#define C4_ 0.886227f
#define C5_ 0.247708f

#define NBATCH 64
#define WH (512 * 512)
#define V4_PER_PLANE (WH / 4)          // 65536 float4 per plane
#define V4_PER_THREAD 4
#define THREADS 128
#define BLOCKS_X (V4_PER_PLANE / (THREADS * V4_PER_THREAD))  // 128

__device__ __forceinline__ void pin4(float4& v) {
    asm volatile("" : "+f"(v.x), "+f"(v.y), "+f"(v.z), "+f"(v.w));
}

__device__ __forceinline__ float quad(float x, float y, float z,
                                      float c0, float c1, float c2, float c3,
                                      float c4, float c5, float c6, float c7,
                                      float c8, float c9) {
    return fmaf(c0, x * x, fmaf(c1, y * y, fmaf(c2, z * z,
           fmaf(c3, x * y, fmaf(c4, x * z, fmaf(c5, y * z,
           fmaf(c6, x, fmaf(c7, y, fmaf(c8, z, c9)))))))));
}

__global__ void __launch_bounds__(THREADS) shade_kernel(
    const float* __restrict__ light,    // [B,9]
    const float* __restrict__ normals,  // [B,3,512,512]
    float* __restrict__ out             // [B,1,512,512]
) {
    int b = blockIdx.y;

    // Coefficients from light — warp-uniform loads (L1-hit broadcast).
    const float* L = light + b * 9;
    float L0 = __ldg(L + 0), L1 = __ldg(L + 1), L2 = __ldg(L + 2);
    float L3 = __ldg(L + 3), L4 = __ldg(L + 4), L5 = __ldg(L + 5);
    float L6 = __ldg(L + 6), L7 = __ldg(L + 7), L8 = __ldg(L + 8);

    float c0 = C1_ * L8;                // M00 (x^2)
    float c1 = -C1_ * L8;               // M11 (y^2)
    float c2 = C3_ * L6;                // M22 (z^2)
    float c3 = 2.0f * C1_ * L4;         // 2*M01 (xy)
    float c4 = 2.0f * C1_ * L7;         // 2*M02 (xz)
    float c5 = 2.0f * C1_ * L5;         // 2*M12 (yz)
    float c6 = 2.0f * C2_ * L3;         // 2*M03 (x)
    float c7 = 2.0f * C2_ * L1;         // 2*M13 (y)
    float c8 = 2.0f * C2_ * L2;         // 2*M23 (z)
    float c9 = C4_ * L0 - C5_ * L6;     // M33 (const)

    // Each block covers THREADS*V4_PER_THREAD = 512 contiguous float4s.
    int v0 = blockIdx.x * (THREADS * V4_PER_THREAD) + threadIdx.x;

    const float4* px = (const float4*)(normals + (size_t)b * 3 * WH);
    const float4* py = px + V4_PER_PLANE;
    const float4* pz = py + V4_PER_PLANE;
    float4* po = (float4*)(out + (size_t)b * WH);

    // Front-batch all 12 streaming loads.
    float4 xv[V4_PER_THREAD], yv[V4_PER_THREAD], zv[V4_PER_THREAD];
#pragma unroll
    for (int i = 0; i < V4_PER_THREAD; i++) xv[i] = __ldg(px + v0 + i * THREADS);
#pragma unroll
    for (int i = 0; i < V4_PER_THREAD; i++) yv[i] = __ldg(py + v0 + i * THREADS);
#pragma unroll
    for (int i = 0; i < V4_PER_THREAD; i++) zv[i] = __ldg(pz + v0 + i * THREADS);

    // Liveness barrier: every loaded value must materialize in a register
    // here — ptxas cannot sink any LDG past its pin.
#pragma unroll
    for (int i = 0; i < V4_PER_THREAD; i++) { pin4(xv[i]); pin4(yv[i]); pin4(zv[i]); }

#pragma unroll
    for (int i = 0; i < V4_PER_THREAD; i++) {
        float4 r;
        r.x = quad(xv[i].x, yv[i].x, zv[i].x, c0,c1,c2,c3,c4,c5,c6,c7,c8,c9);
        r.y = quad(xv[i].y, yv[i].y, zv[i].y, c0,c1,c2,c3,c4,c5,c6,c7,c8,c9);
        r.z = quad(xv[i].z, yv[i].z, zv[i].z, c0,c1,c2,c3,c4,c5,c6,c7,c8,c9);
        r.w = quad(xv[i].w, yv[i].w, zv[i].w, c0,c1,c2,c3,c4,c5,c6,c7,c8,c9);
        po[v0 + i * THREADS] = r;
    }
}

extern "C" void kernel_launch(void* const* d_in, const int* in_sizes, int n_in,
                              void* d_out, int out_size) {
    const float* light = (const float*)d_in[0];     // [64,9]
    const float* normals = (const float*)d_in[1];   // [64,3,512,512]
    float* out = (float*)d_out;                     // [64,1,512,512]

    dim3 grid(BLOCKS_X, NBATCH);  // (128, 64)
    shade_kernel<<<grid, THREADS>>>(light, normals, out);
}

// round 15
// speedup vs baseline: 1.0324x; 1.0324x over previous
#include <cuda_runtime.h>
#include <cstdint>

// Fused quadratic-form SH shading: out[b,p] = n4^T M(b) n4, n4=(nx,ny,nz,1).
// M symmetric -> 10 coefficients computed per-thread from light[b,0..8]
// (warp-uniform loads). Pure HBM stream. A SINGLE asm liveness barrier pins
// all 12 loaded float4s (24 x u64 operands) simultaneously, so ptxas must
// issue all 12 LDG.128 before any FMA — true SASS-level MLP=12.

#define C1_ 0.429043f
#define C2_ 0.511664f
#define C3_ 0.743152f
#define C4_ 0.886227f
#define C5_ 0.247708f

#define NBATCH 64
#define WH (512 * 512)
#define V4_PER_PLANE (WH / 4)          // 65536 float4 per plane
#define V4_PER_THREAD 4
#define THREADS 128
#define BLOCKS_X (V4_PER_PLANE / (THREADS * V4_PER_THREAD))  // 128

__device__ __forceinline__ float quad(float x, float y, float z,
                                      float c0, float c1, float c2, float c3,
                                      float c4, float c5, float c6, float c7,
                                      float c8, float c9) {
    return fmaf(c0, x * x, fmaf(c1, y * y, fmaf(c2, z * z,
           fmaf(c3, x * y, fmaf(c4, x * z, fmaf(c5, y * z,
           fmaf(c6, x, fmaf(c7, y, fmaf(c8, z, c9)))))))));
}

__global__ void __launch_bounds__(THREADS) shade_kernel(
    const float* __restrict__ light,    // [B,9]
    const float* __restrict__ normals,  // [B,3,512,512]
    float* __restrict__ out             // [B,1,512,512]
) {
    int b = blockIdx.y;

    // Coefficients from light — warp-uniform loads (L1-hit broadcast).
    const float* L = light + b * 9;
    float L0 = __ldg(L + 0), L1 = __ldg(L + 1), L2 = __ldg(L + 2);
    float L3 = __ldg(L + 3), L4 = __ldg(L + 4), L5 = __ldg(L + 5);
    float L6 = __ldg(L + 6), L7 = __ldg(L + 7), L8 = __ldg(L + 8);

    float c0 = C1_ * L8;                // M00 (x^2)
    float c1 = -C1_ * L8;               // M11 (y^2)
    float c2 = C3_ * L6;                // M22 (z^2)
    float c3 = 2.0f * C1_ * L4;         // 2*M01 (xy)
    float c4 = 2.0f * C1_ * L7;         // 2*M02 (xz)
    float c5 = 2.0f * C1_ * L5;         // 2*M12 (yz)
    float c6 = 2.0f * C2_ * L3;         // 2*M03 (x)
    float c7 = 2.0f * C2_ * L1;         // 2*M13 (y)
    float c8 = 2.0f * C2_ * L2;         // 2*M23 (z)
    float c9 = C4_ * L0 - C5_ * L6;     // M33 (const)

    // Each block covers THREADS*V4_PER_THREAD = 512 contiguous float4s.
    int v0 = blockIdx.x * (THREADS * V4_PER_THREAD) + threadIdx.x;

    const float4* px = (const float4*)(normals + (size_t)b * 3 * WH);
    const float4* py = px + V4_PER_PLANE;
    const float4* pz = py + V4_PER_PLANE;
    float4* po = (float4*)(out + (size_t)b * WH);

    // Front-batch all 12 streaming loads.
    float4 xv[V4_PER_THREAD], yv[V4_PER_THREAD], zv[V4_PER_THREAD];
#pragma unroll
    for (int i = 0; i < V4_PER_THREAD; i++) xv[i] = __ldg(px + v0 + i * THREADS);
#pragma unroll
    for (int i = 0; i < V4_PER_THREAD; i++) yv[i] = __ldg(py + v0 + i * THREADS);
#pragma unroll
    for (int i = 0; i < V4_PER_THREAD; i++) zv[i] = __ldg(pz + v0 + i * THREADS);

    // SINGLE liveness barrier: all 12 float4s (as 24 u64 halves) must be
    // simultaneously live in registers here. ptxas cannot sink ANY of the
    // 12 LDG.128 past this point or interleave compute before it.
    {
        uint64_t* p = reinterpret_cast<uint64_t*>(xv);  // xv,yv,zv contiguous? not guaranteed
        // Pin each array with its own operands inside ONE asm statement.
        uint64_t* qx = reinterpret_cast<uint64_t*>(xv);
        uint64_t* qy = reinterpret_cast<uint64_t*>(yv);
        uint64_t* qz = reinterpret_cast<uint64_t*>(zv);
        (void)p;
        asm volatile(""
            : "+l"(qx[0]), "+l"(qx[1]), "+l"(qx[2]), "+l"(qx[3]),
              "+l"(qx[4]), "+l"(qx[5]), "+l"(qx[6]), "+l"(qx[7]),
              "+l"(qy[0]), "+l"(qy[1]), "+l"(qy[2]), "+l"(qy[3]),
              "+l"(qy[4]), "+l"(qy[5]), "+l"(qy[6]), "+l"(qy[7]),
              "+l"(qz[0]), "+l"(qz[1]), "+l"(qz[2]), "+l"(qz[3]),
              "+l"(qz[4]), "+l"(qz[5]), "+l"(qz[6]), "+l"(qz[7]));
    }

#pragma unroll
    for (int i = 0; i < V4_PER_THREAD; i++) {
        float4 r;
        r.x = quad(xv[i].x, yv[i].x, zv[i].x, c0,c1,c2,c3,c4,c5,c6,c7,c8,c9);
        r.y = quad(xv[i].y, yv[i].y, zv[i].y, c0,c1,c2,c3,c4,c5,c6,c7,c8,c9);
        r.z = quad(xv[i].z, yv[i].z, zv[i].z, c0,c1,c2,c3,c4,c5,c6,c7,c8,c9);
        r.w = quad(xv[i].w, yv[i].w, zv[i].w, c0,c1,c2,c3,c4,c5,c6,c7,c8,c9);
        po[v0 + i * THREADS] = r;
    }
}

extern "C" void kernel_launch(void* const* d_in, const int* in_sizes, int n_in,
                              void* d_out, int out_size) {
    const float* light = (const float*)d_in[0];     // [64,9]
    const float* normals = (const float*)d_in[1];   // [64,3,512,512]
    float* out = (float*)d_out;                     // [64,1,512,512]

    dim3 grid(BLOCKS_X, NBATCH);  // (128, 64)
    shade_kernel<<<grid, THREADS>>>(light, normals, out);
}